// round 12
// baseline (speedup 1.0000x reference)
#include <cuda_runtime.h>
#include <cuda_fp16.h>
#include <cstdint>

// ---------------------------------------------------------------------------
// Problem constants
// ---------------------------------------------------------------------------
#define BDIM 4096
#define LDIM 4096
#define HDIM 1024

// GEMM tiling: CTA tile 128x128, 4 warps of 64x64, BK=64 (fp16), 3 stages
#define BM 128
#define BN 128
#define BK 64
#define KT_CNT (HDIM / BK)        // 16 k-chunks
#define STAGES 3
#define TILE_BYTES (BM * BK * 2)  // 16384 B (128 rows x 128B)
#define STAGE_BYTES (2 * TILE_BYTES)          // A + B = 32768
#define SMEM_BYTES (STAGES * STAGE_BYTES)     // 98304 B -> 2 CTAs/SM

// ---------------------------------------------------------------------------
// Device scratch: pre-converted fp16, k pair-permuted within each 16-group:
// half2 pairs stored [p0,p4,p1,p5,p2,p6,p3,p7] so one LDS.64 at pair-slot 2t
// yields (k=2t,2t+1) and (k=2t+8,2t+9) = (a0,a2)/(a1,a3)/(b0,b1).
// ---------------------------------------------------------------------------
__device__ float g_diag[LDIM];
__device__ __half g_xh[BDIM * HDIM];
__device__ __half g_wh[LDIM * HDIM];

// ---------------------------------------------------------------------------
// Helpers
// ---------------------------------------------------------------------------
__device__ __forceinline__ void mma_fp16(float& c0, float& c1, float& c2, float& c3,
                                         uint32_t a0, uint32_t a1, uint32_t a2, uint32_t a3,
                                         uint32_t b0, uint32_t b1) {
    asm volatile(
        "mma.sync.aligned.m16n8k16.row.col.f32.f16.f16.f32 "
        "{%0,%1,%2,%3}, {%4,%5,%6,%7}, {%8,%9}, {%0,%1,%2,%3};\n"
        : "+f"(c0), "+f"(c1), "+f"(c2), "+f"(c3)
        : "r"(a0), "r"(a1), "r"(a2), "r"(a3), "r"(b0), "r"(b1));
}

__device__ __forceinline__ void cp_async16(void* smem_ptr, const void* gptr) {
    uint32_t saddr = (uint32_t)__cvta_generic_to_shared(smem_ptr);
    asm volatile("cp.async.cg.shared.global [%0], [%1], 16;\n" :: "r"(saddr), "l"(gptr));
}
__device__ __forceinline__ void cp_commit() {
    asm volatile("cp.async.commit_group;\n" ::: "memory");
}
template <int N>
__device__ __forceinline__ void cp_wait() {
    asm volatile("cp.async.wait_group %0;\n" :: "n"(N) : "memory");
}

// ---------------------------------------------------------------------------
// fp32 -> fp16 pair-permuted convert of one 16-float group; _dot variant also
// returns dot(group_w, group_e) in fp32 for the diag fusion.
// ---------------------------------------------------------------------------
__device__ __forceinline__ void convert16(const float* __restrict__ src,
                                          __half* __restrict__ dst, size_t gi) {
    const float4* s = reinterpret_cast<const float4*>(src) + 4 * gi;
    float4 v0 = s[0], v1 = s[1], v2 = s[2], v3 = s[3];
    uint32_t p[8];
    __half2 h;
    h = __floats2half2_rn(v0.x, v0.y); p[0] = *reinterpret_cast<uint32_t*>(&h);
    h = __floats2half2_rn(v0.z, v0.w); p[1] = *reinterpret_cast<uint32_t*>(&h);
    h = __floats2half2_rn(v1.x, v1.y); p[2] = *reinterpret_cast<uint32_t*>(&h);
    h = __floats2half2_rn(v1.z, v1.w); p[3] = *reinterpret_cast<uint32_t*>(&h);
    h = __floats2half2_rn(v2.x, v2.y); p[4] = *reinterpret_cast<uint32_t*>(&h);
    h = __floats2half2_rn(v2.z, v2.w); p[5] = *reinterpret_cast<uint32_t*>(&h);
    h = __floats2half2_rn(v3.x, v3.y); p[6] = *reinterpret_cast<uint32_t*>(&h);
    h = __floats2half2_rn(v3.z, v3.w); p[7] = *reinterpret_cast<uint32_t*>(&h);
    reinterpret_cast<uint4*>(dst)[2 * gi + 0] = make_uint4(p[0], p[4], p[1], p[5]);
    reinterpret_cast<uint4*>(dst)[2 * gi + 1] = make_uint4(p[2], p[6], p[3], p[7]);
}

__device__ __forceinline__ float convert16_dot(const float* __restrict__ w,
                                               const float* __restrict__ e,
                                               __half* __restrict__ dst, size_t gi) {
    const float4* s = reinterpret_cast<const float4*>(w) + 4 * gi;
    const float4* es = reinterpret_cast<const float4*>(e) + 4 * gi;
    float4 v0 = s[0], v1 = s[1], v2 = s[2], v3 = s[3];
    float4 e0 = es[0], e1 = es[1], e2 = es[2], e3 = es[3];
    uint32_t p[8];
    __half2 h;
    h = __floats2half2_rn(v0.x, v0.y); p[0] = *reinterpret_cast<uint32_t*>(&h);
    h = __floats2half2_rn(v0.z, v0.w); p[1] = *reinterpret_cast<uint32_t*>(&h);
    h = __floats2half2_rn(v1.x, v1.y); p[2] = *reinterpret_cast<uint32_t*>(&h);
    h = __floats2half2_rn(v1.z, v1.w); p[3] = *reinterpret_cast<uint32_t*>(&h);
    h = __floats2half2_rn(v2.x, v2.y); p[4] = *reinterpret_cast<uint32_t*>(&h);
    h = __floats2half2_rn(v2.z, v2.w); p[5] = *reinterpret_cast<uint32_t*>(&h);
    h = __floats2half2_rn(v3.x, v3.y); p[6] = *reinterpret_cast<uint32_t*>(&h);
    h = __floats2half2_rn(v3.z, v3.w); p[7] = *reinterpret_cast<uint32_t*>(&h);
    reinterpret_cast<uint4*>(dst)[2 * gi + 0] = make_uint4(p[0], p[4], p[1], p[5]);
    reinterpret_cast<uint4*>(dst)[2 * gi + 1] = make_uint4(p[2], p[6], p[3], p[7]);
    float d = 0.f;
    d += v0.x * e0.x + v0.y * e0.y + v0.z * e0.z + v0.w * e0.w;
    d += v1.x * e1.x + v1.y * e1.y + v1.z * e1.z + v1.w * e1.w;
    d += v2.x * e2.x + v2.y * e2.y + v2.z * e2.z + v2.w * e2.w;
    d += v3.x * e3.x + v3.y * e3.y + v3.z * e3.z + v3.w * e3.w;
    return d;
}

// ---------------------------------------------------------------------------
// Fused prep, heavy blocks FIRST: blocks [0,512) convert W rows (one warp per
// row) + diag[row] = dot(E,W)+b; blocks [512,1536) convert x (tail filler).
// ---------------------------------------------------------------------------
__global__ void prep_kernel(const float* __restrict__ x,
                            const float* __restrict__ E,
                            const float* __restrict__ W,
                            const float* __restrict__ b) {
    if (blockIdx.x < 512) {
        const int lane = threadIdx.x & 31;
        const int row = blockIdx.x * 8 + (threadIdx.x >> 5);
        size_t gi = (size_t)row * (HDIM / 16) + lane * 2;     // 2 groups/lane
        float d = convert16_dot(W, E, g_wh, gi)
                + convert16_dot(W, E, g_wh, gi + 1);
#pragma unroll
        for (int o = 16; o > 0; o >>= 1)
            d += __shfl_down_sync(0xffffffffu, d, o);
        if (lane == 0) g_diag[row] = d + b[row];
    } else {
        size_t gi = (size_t)(blockIdx.x - 512) * 256 + threadIdx.x;  // 262144 groups
        convert16(x, g_xh, gi);
    }
}

// ---------------------------------------------------------------------------
// Kernel: C[m,n] = sum_k X[m,k]*W[n,k] + diag[n]
// fp16 mma m16n8k16, 4 warps x (64x64), 3-stage cp.async spread across the
// chunk (one quarter per ks block), XOR-swizzled 128B rows, fragment
// double-buffer, single barrier per chunk.
// ---------------------------------------------------------------------------
__global__ void __launch_bounds__(128, 2)
gemm_fp16_kernel(float* __restrict__ C) {
    extern __shared__ char smem[];

    const int tid = threadIdx.x;
    const int lane = tid & 31;
    const int wid = tid >> 5;       // 0..3
    const int warp_m = wid >> 1;    // 0..1
    const int warp_n = wid & 1;     // 0..1

    const int m0 = blockIdx.y * BM;
    const int n0 = blockIdx.x * BN;

    const __half* Ag = g_xh + (size_t)m0 * HDIM;
    const __half* Bg = g_wh + (size_t)n0 * HDIM;

    // Load one quarter (rows 32q..32q+31) of stage s from chunk kt.
    auto load_quarter = [&](int s, int kt, int q) {
        char* as = smem + s * STAGE_BYTES;
        char* bs = as + TILE_BYTES;
        const int k0 = kt * BK;
#pragma unroll
        for (int jj = 0; jj < 2; jj++) {
            int c = (2 * q + jj) * 128 + tid;   // 0..1023 over all quarters
            int row = c >> 3;                   // 0..127
            int ch = c & 7;                     // 16B chunk
            int g = ch >> 1, h = ch & 1;
            uint32_t dst = (uint32_t)(row * 128 + (((g ^ (row & 3)) << 1) | h) * 16);
            cp_async16(as + dst, Ag + (size_t)row * HDIM + k0 + ch * 8);
            cp_async16(bs + dst, Bg + (size_t)row * HDIM + k0 + ch * 8);
        }
    };
    auto load_stage = [&](int s, int kt) {
#pragma unroll
        for (int q = 0; q < 4; q++) load_quarter(s, kt, q);
        cp_commit();
    };

    float acc[32][4];
#pragma unroll
    for (int i = 0; i < 32; i++)
#pragma unroll
        for (int j = 0; j < 4; j++) acc[i][j] = 0.f;

    // Fragment base offsets (swizzle group field = bits [5:6])
    const int t2 = (lane & 3) * 8;
    uint32_t abase[4], bbase[8];
#pragma unroll
    for (int mt = 0; mt < 4; mt++) {
        int r = warp_m * 64 + mt * 16 + (lane >> 2);
        abase[mt] = (uint32_t)(r * 128 + ((r & 3) << 5) + t2);
    }
#pragma unroll
    for (int nt = 0; nt < 8; nt++) {
        int n = warp_n * 64 + nt * 8 + (lane >> 2);
        bbase[nt] = (uint32_t)(n * 128 + ((n & 3) << 5) + t2);
    }

    // Double-buffered fragments
    uint2 afr[2][4][2];
    uint2 bfr[2][8];

    // Prologue: stages 0..1 committed
#pragma unroll
    for (int s = 0; s < STAGES - 1; s++) load_stage(s, s);

    for (int kt = 0; kt < KT_CNT; kt++) {
        cp_wait<STAGES - 2>();
        __syncthreads();   // sole barrier: orders prior-stage reads before overwrite

        const char* as = smem + (kt % STAGES) * STAGE_BYTES;
        const char* bs = as + TILE_BYTES;
        const int snext = (kt + STAGES - 1) % STAGES;
        const bool more = (kt + STAGES - 1 < KT_CNT);

        // ks=0 fragments first (tensor pipe needs them immediately)
#pragma unroll
        for (int mt = 0; mt < 4; mt++) {
            afr[0][mt][0] = *reinterpret_cast<const uint2*>(as + abase[mt]);
            afr[0][mt][1] = *reinterpret_cast<const uint2*>(as + abase[mt] + 8 * 128);
        }
#pragma unroll
        for (int nt = 0; nt < 8; nt++)
            bfr[0][nt] = *reinterpret_cast<const uint2*>(bs + bbase[nt]);

#pragma unroll
        for (int ks = 0; ks < BK / 16; ks++) {   // 4 k16-groups
            const int cur = ks & 1;
            // Spread next-stage global loads: one quarter per ks block
            if (more) load_quarter(snext, kt + STAGES - 1, ks);
            // Prefetch ks+1 fragments
            if (ks < BK / 16 - 1) {
                const int nxt = (ks + 1) & 1;
                const uint32_t xr = (uint32_t)((ks + 1) << 5);
#pragma unroll
                for (int mt = 0; mt < 4; mt++) {
                    uint32_t off = abase[mt] ^ xr;
                    afr[nxt][mt][0] = *reinterpret_cast<const uint2*>(as + off);
                    afr[nxt][mt][1] = *reinterpret_cast<const uint2*>(as + off + 8 * 128);
                }
#pragma unroll
                for (int nt = 0; nt < 8; nt++)
                    bfr[nxt][nt] = *reinterpret_cast<const uint2*>(bs + (bbase[nt] ^ xr));
            }
#pragma unroll
            for (int mt = 0; mt < 4; mt++)
#pragma unroll
                for (int nt = 0; nt < 8; nt++)
                    mma_fp16(acc[mt * 8 + nt][0], acc[mt * 8 + nt][1],
                             acc[mt * 8 + nt][2], acc[mt * 8 + nt][3],
                             afr[cur][mt][0].x, afr[cur][mt][1].x,
                             afr[cur][mt][0].y, afr[cur][mt][1].y,
                             bfr[cur][nt].x, bfr[cur][nt].y);
        }
        cp_commit();   // one group per chunk (empty when !more keeps count aligned)
    }

    // Epilogue: + diag[n], float2 stores
#pragma unroll
    for (int mt = 0; mt < 4; mt++) {
#pragma unroll
        for (int nt = 0; nt < 8; nt++) {
            int r = m0 + warp_m * 64 + mt * 16 + (lane >> 2);
            int c = n0 + warp_n * 64 + nt * 8 + 2 * (lane & 3);
            float2 dg = *reinterpret_cast<const float2*>(&g_diag[c]);
            float2 v0 = make_float2(acc[mt * 8 + nt][0] + dg.x,
                                    acc[mt * 8 + nt][1] + dg.y);
            float2 v1 = make_float2(acc[mt * 8 + nt][2] + dg.x,
                                    acc[mt * 8 + nt][3] + dg.y);
            *reinterpret_cast<float2*>(C + (size_t)r * LDIM + c) = v0;
            *reinterpret_cast<float2*>(C + (size_t)(r + 8) * LDIM + c) = v1;
        }
    }
}

// ---------------------------------------------------------------------------
// Launch
// ---------------------------------------------------------------------------
extern "C" void kernel_launch(void* const* d_in, const int* in_sizes, int n_in,
                              void* d_out, int out_size) {
    const float* x = (const float*)d_in[0];   // bert_output [B,H]
    const float* E = (const float*)d_in[1];   // label_embed [L,H]
    const float* W = (const float*)d_in[2];   // W [L,H]
    const float* b = (const float*)d_in[3];   // b [L]
    float* out = (float*)d_out;               // [B,L]

    prep_kernel<<<1536, 256>>>(x, E, W, b);

    cudaFuncSetAttribute(gemm_fp16_kernel,
                         cudaFuncAttributeMaxDynamicSharedMemorySize, SMEM_BYTES);
    dim3 grid(LDIM / BN, BDIM / BM);
    gemm_fp16_kernel<<<grid, 128, SMEM_BYTES>>>(out);
}

// round 13
// speedup vs baseline: 1.1471x; 1.1471x over previous
#include <cuda_runtime.h>
#include <cuda_fp16.h>
#include <cstdint>

// ---------------------------------------------------------------------------
// Problem constants
// ---------------------------------------------------------------------------
#define BDIM 4096
#define LDIM 4096
#define HDIM 1024

// GEMM tiling: CTA tile 128x128, 4 warps of 64x64, BK=64 (fp16), 3 stages
#define BM 128
#define BN 128
#define BK 64
#define KT_CNT (HDIM / BK)        // 16 k-chunks
#define STAGES 3
#define TILE_BYTES (BM * BK * 2)  // 16384 B (128 rows x 128B)
#define STAGE_BYTES (2 * TILE_BYTES)          // A + B = 32768
#define SMEM_BYTES (STAGES * STAGE_BYTES)     // 98304 B -> 2 CTAs/SM

// ---------------------------------------------------------------------------
// Device scratch: pre-converted fp16, k pair-permuted within each 16-group:
// half2 pairs stored [p0,p4,p1,p5,p2,p6,p3,p7] so one LDS.64 at pair-slot 2t
// yields (k=2t,2t+1) and (k=2t+8,2t+9) = (a0,a2)/(a1,a3)/(b0,b1).
// ---------------------------------------------------------------------------
__device__ float g_diag[LDIM];
__device__ __half g_xh[BDIM * HDIM];
__device__ __half g_wh[LDIM * HDIM];

// ---------------------------------------------------------------------------
// Helpers
// ---------------------------------------------------------------------------
__device__ __forceinline__ void mma_fp16(float& c0, float& c1, float& c2, float& c3,
                                         uint32_t a0, uint32_t a1, uint32_t a2, uint32_t a3,
                                         uint32_t b0, uint32_t b1) {
    asm volatile(
        "mma.sync.aligned.m16n8k16.row.col.f32.f16.f16.f32 "
        "{%0,%1,%2,%3}, {%4,%5,%6,%7}, {%8,%9}, {%0,%1,%2,%3};\n"
        : "+f"(c0), "+f"(c1), "+f"(c2), "+f"(c3)
        : "r"(a0), "r"(a1), "r"(a2), "r"(a3), "r"(b0), "r"(b1));
}

__device__ __forceinline__ void cp_async16(void* smem_ptr, const void* gptr) {
    uint32_t saddr = (uint32_t)__cvta_generic_to_shared(smem_ptr);
    asm volatile("cp.async.cg.shared.global [%0], [%1], 16;\n" :: "r"(saddr), "l"(gptr));
}
__device__ __forceinline__ void cp_commit() {
    asm volatile("cp.async.commit_group;\n" ::: "memory");
}
template <int N>
__device__ __forceinline__ void cp_wait() {
    asm volatile("cp.async.wait_group %0;\n" :: "n"(N) : "memory");
}

// ---------------------------------------------------------------------------
// fp32 -> fp16 pair-permuted convert of one 16-float group.
// ---------------------------------------------------------------------------
__device__ __forceinline__ void convert16(const float* __restrict__ src,
                                          __half* __restrict__ dst, size_t gi) {
    const float4* s = reinterpret_cast<const float4*>(src) + 4 * gi;
    float4 v0 = s[0], v1 = s[1], v2 = s[2], v3 = s[3];
    uint32_t p[8];
    __half2 h;
    h = __floats2half2_rn(v0.x, v0.y); p[0] = *reinterpret_cast<uint32_t*>(&h);
    h = __floats2half2_rn(v0.z, v0.w); p[1] = *reinterpret_cast<uint32_t*>(&h);
    h = __floats2half2_rn(v1.x, v1.y); p[2] = *reinterpret_cast<uint32_t*>(&h);
    h = __floats2half2_rn(v1.z, v1.w); p[3] = *reinterpret_cast<uint32_t*>(&h);
    h = __floats2half2_rn(v2.x, v2.y); p[4] = *reinterpret_cast<uint32_t*>(&h);
    h = __floats2half2_rn(v2.z, v2.w); p[5] = *reinterpret_cast<uint32_t*>(&h);
    h = __floats2half2_rn(v3.x, v3.y); p[6] = *reinterpret_cast<uint32_t*>(&h);
    h = __floats2half2_rn(v3.z, v3.w); p[7] = *reinterpret_cast<uint32_t*>(&h);
    reinterpret_cast<uint4*>(dst)[2 * gi + 0] = make_uint4(p[0], p[4], p[1], p[5]);
    reinterpret_cast<uint4*>(dst)[2 * gi + 1] = make_uint4(p[2], p[6], p[3], p[7]);
}

// ---------------------------------------------------------------------------
// Prep A: diag[j] = sum_k E[j,k]*W[j,k] + b[j]   (fp32 exact, one warp/row)
// ---------------------------------------------------------------------------
__global__ void diag_kernel(const float* __restrict__ E,
                            const float* __restrict__ W,
                            const float* __restrict__ b) {
    int warp = (blockIdx.x * blockDim.x + threadIdx.x) >> 5;
    int lane = threadIdx.x & 31;
    if (warp >= LDIM) return;
    const float4* e4 = reinterpret_cast<const float4*>(E + (size_t)warp * HDIM);
    const float4* w4 = reinterpret_cast<const float4*>(W + (size_t)warp * HDIM);
    float sum = 0.f;
#pragma unroll
    for (int i = 0; i < HDIM / 4 / 32; i++) {
        float4 e = e4[lane + i * 32];
        float4 w = w4[lane + i * 32];
        sum += e.x * w.x + e.y * w.y + e.z * w.z + e.w * w.w;
    }
#pragma unroll
    for (int o = 16; o > 0; o >>= 1)
        sum += __shfl_down_sync(0xffffffffu, sum, o);
    if (lane == 0) g_diag[warp] = sum + b[warp];
}

// ---------------------------------------------------------------------------
// Prep B: single uniform convert kernel — blocks [0,1024) convert x,
// blocks [1024,2048) convert W. Identical per-block work, no warp divergence.
// ---------------------------------------------------------------------------
__global__ void convert_kernel(const float* __restrict__ x,
                               const float* __restrict__ W) {
    if (blockIdx.x < 1024) {
        size_t gi = (size_t)blockIdx.x * 256 + threadIdx.x;           // x groups
        convert16(x, g_xh, gi);
    } else {
        size_t gi = (size_t)(blockIdx.x - 1024) * 256 + threadIdx.x;  // W groups
        convert16(W, g_wh, gi);
    }
}

// ---------------------------------------------------------------------------
// Kernel: C[m,n] = sum_k X[m,k]*W[n,k] + diag[n]
// fp16 mma m16n8k16, 4 warps x (64x64), 3-stage cp.async, BK=64,
// XOR-swizzled 128B rows, ks-level fragment double-buffer,
// single barrier per chunk.   (R11 gemm — best measured: 98.6 us)
// ---------------------------------------------------------------------------
__global__ void __launch_bounds__(128, 2)
gemm_fp16_kernel(float* __restrict__ C) {
    extern __shared__ char smem[];

    const int tid = threadIdx.x;
    const int lane = tid & 31;
    const int wid = tid >> 5;       // 0..3
    const int warp_m = wid >> 1;    // 0..1
    const int warp_n = wid & 1;     // 0..1

    const int m0 = blockIdx.y * BM;
    const int n0 = blockIdx.x * BN;

    const __half* Ag = g_xh + (size_t)m0 * HDIM;
    const __half* Bg = g_wh + (size_t)n0 * HDIM;

    auto load_stage = [&](int s, int kt) {
        char* as = smem + s * STAGE_BYTES;
        char* bs = as + TILE_BYTES;
        const int k0 = kt * BK;
#pragma unroll
        for (int j = 0; j < 8; j++) {
            int c = j * 128 + tid;        // 0..1023
            int row = c >> 3;             // 0..127
            int ch = c & 7;               // 16B chunk
            int g = ch >> 1, h = ch & 1;
            uint32_t dst = (uint32_t)(row * 128 + (((g ^ (row & 3)) << 1) | h) * 16);
            cp_async16(as + dst, Ag + (size_t)row * HDIM + k0 + ch * 8);
            cp_async16(bs + dst, Bg + (size_t)row * HDIM + k0 + ch * 8);
        }
        cp_commit();
    };

    float acc[32][4];
#pragma unroll
    for (int i = 0; i < 32; i++)
#pragma unroll
        for (int j = 0; j < 4; j++) acc[i][j] = 0.f;

    // Fragment base offsets (swizzle group field = bits [5:6])
    const int t2 = (lane & 3) * 8;
    uint32_t abase[4], bbase[8];
#pragma unroll
    for (int mt = 0; mt < 4; mt++) {
        int r = warp_m * 64 + mt * 16 + (lane >> 2);
        abase[mt] = (uint32_t)(r * 128 + ((r & 3) << 5) + t2);
    }
#pragma unroll
    for (int nt = 0; nt < 8; nt++) {
        int n = warp_n * 64 + nt * 8 + (lane >> 2);
        bbase[nt] = (uint32_t)(n * 128 + ((n & 3) << 5) + t2);
    }

    // Double-buffered fragments
    uint2 afr[2][4][2];
    uint2 bfr[2][8];

    // Prologue: stages 0..1 in flight
#pragma unroll
    for (int s = 0; s < STAGES - 1; s++) load_stage(s, s);

    for (int kt = 0; kt < KT_CNT; kt++) {
        cp_wait<STAGES - 2>();
        __syncthreads();   // sole barrier: orders prior-stage reads before overwrite

        if (kt + STAGES - 1 < KT_CNT)
            load_stage((kt + STAGES - 1) % STAGES, kt + STAGES - 1);
        else
            cp_commit();   // keep group count consistent

        const char* as = smem + (kt % STAGES) * STAGE_BYTES;
        const char* bs = as + TILE_BYTES;

        // Load ks=0 fragments into buffer 0
#pragma unroll
        for (int mt = 0; mt < 4; mt++) {
            afr[0][mt][0] = *reinterpret_cast<const uint2*>(as + abase[mt]);
            afr[0][mt][1] = *reinterpret_cast<const uint2*>(as + abase[mt] + 8 * 128);
        }
#pragma unroll
        for (int nt = 0; nt < 8; nt++)
            bfr[0][nt] = *reinterpret_cast<const uint2*>(bs + bbase[nt]);

#pragma unroll
        for (int ks = 0; ks < BK / 16; ks++) {   // 4 k16-groups
            const int cur = ks & 1;
            // Prefetch ks+1 fragments before this group's mma block
            if (ks < BK / 16 - 1) {
                const int nxt = (ks + 1) & 1;
                const uint32_t xr = (uint32_t)((ks + 1) << 5);
#pragma unroll
                for (int mt = 0; mt < 4; mt++) {
                    uint32_t off = abase[mt] ^ xr;
                    afr[nxt][mt][0] = *reinterpret_cast<const uint2*>(as + off);
                    afr[nxt][mt][1] = *reinterpret_cast<const uint2*>(as + off + 8 * 128);
                }
#pragma unroll
                for (int nt = 0; nt < 8; nt++)
                    bfr[nxt][nt] = *reinterpret_cast<const uint2*>(bs + (bbase[nt] ^ xr));
            }
#pragma unroll
            for (int mt = 0; mt < 4; mt++)
#pragma unroll
                for (int nt = 0; nt < 8; nt++)
                    mma_fp16(acc[mt * 8 + nt][0], acc[mt * 8 + nt][1],
                             acc[mt * 8 + nt][2], acc[mt * 8 + nt][3],
                             afr[cur][mt][0].x, afr[cur][mt][1].x,
                             afr[cur][mt][0].y, afr[cur][mt][1].y,
                             bfr[cur][nt].x, bfr[cur][nt].y);
        }
        // no end-of-chunk barrier: next iteration's top barrier provides the guard
    }

    // Epilogue: + diag[n], float2 stores
#pragma unroll
    for (int mt = 0; mt < 4; mt++) {
#pragma unroll
        for (int nt = 0; nt < 8; nt++) {
            int r = m0 + warp_m * 64 + mt * 16 + (lane >> 2);
            int c = n0 + warp_n * 64 + nt * 8 + 2 * (lane & 3);
            float2 dg = *reinterpret_cast<const float2*>(&g_diag[c]);
            float2 v0 = make_float2(acc[mt * 8 + nt][0] + dg.x,
                                    acc[mt * 8 + nt][1] + dg.y);
            float2 v1 = make_float2(acc[mt * 8 + nt][2] + dg.x,
                                    acc[mt * 8 + nt][3] + dg.y);
            *reinterpret_cast<float2*>(C + (size_t)r * LDIM + c) = v0;
            *reinterpret_cast<float2*>(C + (size_t)(r + 8) * LDIM + c) = v1;
        }
    }
}

// ---------------------------------------------------------------------------
// Launch
// ---------------------------------------------------------------------------
extern "C" void kernel_launch(void* const* d_in, const int* in_sizes, int n_in,
                              void* d_out, int out_size) {
    const float* x = (const float*)d_in[0];   // bert_output [B,H]
    const float* E = (const float*)d_in[1];   // label_embed [L,H]
    const float* W = (const float*)d_in[2];   // W [L,H]
    const float* b = (const float*)d_in[3];   // b [L]
    float* out = (float*)d_out;               // [B,L]

    diag_kernel<<<LDIM / 8, 256>>>(E, W, b);
    convert_kernel<<<2048, 256>>>(x, W);

    cudaFuncSetAttribute(gemm_fp16_kernel,
                         cudaFuncAttributeMaxDynamicSharedMemorySize, SMEM_BYTES);
    dim3 grid(LDIM / BN, BDIM / BM);
    gemm_fp16_kernel<<<grid, 128, SMEM_BYTES>>>(out);
}

// round 15
// speedup vs baseline: 1.1844x; 1.0325x over previous
#include <cuda_runtime.h>
#include <cuda_fp16.h>
#include <cstdint>

// ---------------------------------------------------------------------------
// Problem constants
// ---------------------------------------------------------------------------
#define BDIM 4096
#define LDIM 4096
#define HDIM 1024

// GEMM tiling: CTA tile 128x128, 4 warps of 64x64, BK=64 (fp16), 3 stages
#define BM 128
#define BN 128
#define BK 64
#define KT_CNT (HDIM / BK)        // 16 k-chunks
#define STAGES 3
#define TILE_BYTES (BM * BK * 2)  // 16384 B (128 rows x 128B)
#define STAGE_BYTES (2 * TILE_BYTES)          // A + B = 32768
#define SMEM_BYTES (STAGES * STAGE_BYTES)     // 98304 B -> 2 CTAs/SM

// ---------------------------------------------------------------------------
// Device scratch: pre-converted fp16, k pair-permuted within each 16-group:
// half2 pairs stored [p0,p4,p1,p5,p2,p6,p3,p7] so one LDS.64 at pair-slot 2t
// yields (k=2t,2t+1) and (k=2t+8,2t+9) = (a0,a2)/(a1,a3)/(b0,b1).
// ---------------------------------------------------------------------------
__device__ float g_diag[LDIM];
__device__ __half g_xh[BDIM * HDIM];
__device__ __half g_wh[LDIM * HDIM];

// ---------------------------------------------------------------------------
// Helpers
// ---------------------------------------------------------------------------
__device__ __forceinline__ void mma_fp16(float& c0, float& c1, float& c2, float& c3,
                                         uint32_t a0, uint32_t a1, uint32_t a2, uint32_t a3,
                                         uint32_t b0, uint32_t b1) {
    asm volatile(
        "mma.sync.aligned.m16n8k16.row.col.f32.f16.f16.f32 "
        "{%0,%1,%2,%3}, {%4,%5,%6,%7}, {%8,%9}, {%0,%1,%2,%3};\n"
        : "+f"(c0), "+f"(c1), "+f"(c2), "+f"(c3)
        : "r"(a0), "r"(a1), "r"(a2), "r"(a3), "r"(b0), "r"(b1));
}

__device__ __forceinline__ void cp_async16(void* smem_ptr, const void* gptr) {
    uint32_t saddr = (uint32_t)__cvta_generic_to_shared(smem_ptr);
    asm volatile("cp.async.cg.shared.global [%0], [%1], 16;\n" :: "r"(saddr), "l"(gptr));
}
__device__ __forceinline__ void cp_commit() {
    asm volatile("cp.async.commit_group;\n" ::: "memory");
}
template <int N>
__device__ __forceinline__ void cp_wait() {
    asm volatile("cp.async.wait_group %0;\n" :: "n"(N) : "memory");
}

// ---------------------------------------------------------------------------
// fp32 -> fp16 pair-permuted convert of one 16-float group; _dot variant also
// returns dot(group_w, group_e) in fp32.
// ---------------------------------------------------------------------------
__device__ __forceinline__ void convert16(const float* __restrict__ src,
                                          __half* __restrict__ dst, size_t gi) {
    const float4* s = reinterpret_cast<const float4*>(src) + 4 * gi;
    float4 v0 = s[0], v1 = s[1], v2 = s[2], v3 = s[3];
    uint32_t p[8];
    __half2 h;
    h = __floats2half2_rn(v0.x, v0.y); p[0] = *reinterpret_cast<uint32_t*>(&h);
    h = __floats2half2_rn(v0.z, v0.w); p[1] = *reinterpret_cast<uint32_t*>(&h);
    h = __floats2half2_rn(v1.x, v1.y); p[2] = *reinterpret_cast<uint32_t*>(&h);
    h = __floats2half2_rn(v1.z, v1.w); p[3] = *reinterpret_cast<uint32_t*>(&h);
    h = __floats2half2_rn(v2.x, v2.y); p[4] = *reinterpret_cast<uint32_t*>(&h);
    h = __floats2half2_rn(v2.z, v2.w); p[5] = *reinterpret_cast<uint32_t*>(&h);
    h = __floats2half2_rn(v3.x, v3.y); p[6] = *reinterpret_cast<uint32_t*>(&h);
    h = __floats2half2_rn(v3.z, v3.w); p[7] = *reinterpret_cast<uint32_t*>(&h);
    reinterpret_cast<uint4*>(dst)[2 * gi + 0] = make_uint4(p[0], p[4], p[1], p[5]);
    reinterpret_cast<uint4*>(dst)[2 * gi + 1] = make_uint4(p[2], p[6], p[3], p[7]);
}

__device__ __forceinline__ float convert16_dot(const float* __restrict__ w,
                                               const float* __restrict__ e,
                                               __half* __restrict__ dst, size_t gi) {
    const float4* s = reinterpret_cast<const float4*>(w) + 4 * gi;
    const float4* es = reinterpret_cast<const float4*>(e) + 4 * gi;
    float4 v0 = s[0], v1 = s[1], v2 = s[2], v3 = s[3];
    float4 e0 = es[0], e1 = es[1], e2 = es[2], e3 = es[3];
    uint32_t p[8];
    __half2 h;
    h = __floats2half2_rn(v0.x, v0.y); p[0] = *reinterpret_cast<uint32_t*>(&h);
    h = __floats2half2_rn(v0.z, v0.w); p[1] = *reinterpret_cast<uint32_t*>(&h);
    h = __floats2half2_rn(v1.x, v1.y); p[2] = *reinterpret_cast<uint32_t*>(&h);
    h = __floats2half2_rn(v1.z, v1.w); p[3] = *reinterpret_cast<uint32_t*>(&h);
    h = __floats2half2_rn(v2.x, v2.y); p[4] = *reinterpret_cast<uint32_t*>(&h);
    h = __floats2half2_rn(v2.z, v2.w); p[5] = *reinterpret_cast<uint32_t*>(&h);
    h = __floats2half2_rn(v3.x, v3.y); p[6] = *reinterpret_cast<uint32_t*>(&h);
    h = __floats2half2_rn(v3.z, v3.w); p[7] = *reinterpret_cast<uint32_t*>(&h);
    reinterpret_cast<uint4*>(dst)[2 * gi + 0] = make_uint4(p[0], p[4], p[1], p[5]);
    reinterpret_cast<uint4*>(dst)[2 * gi + 1] = make_uint4(p[2], p[6], p[3], p[7]);
    float d = 0.f;
    d += v0.x * e0.x + v0.y * e0.y + v0.z * e0.z + v0.w * e0.w;
    d += v1.x * e1.x + v1.y * e1.y + v1.z * e1.z + v1.w * e1.w;
    d += v2.x * e2.x + v2.y * e2.y + v2.z * e2.z + v2.w * e2.w;
    d += v3.x * e3.x + v3.y * e3.y + v3.z * e3.z + v3.w * e3.w;
    return d;
}

// ---------------------------------------------------------------------------
// Single fused prep kernel (2048 blocks):
//   blocks [0,1024):    convert x -> g_xh
//   blocks [1024,2048): convert W -> g_wh  AND  diag[row] = dot(E,W)+b
// Each W block covers 256 groups = 4 rows (64 threads per row; thread's
// group index gi = base + tid, same coalescing as the pure convert).
// Row r of the block is reduced by warps 2r and 2r+1.
// ---------------------------------------------------------------------------
__global__ void prep_kernel(const float* __restrict__ x,
                            const float* __restrict__ E,
                            const float* __restrict__ W,
                            const float* __restrict__ b) {
    __shared__ float red[8];
    if (blockIdx.x < 1024) {
        size_t gi = (size_t)blockIdx.x * 256 + threadIdx.x;
        convert16(x, g_xh, gi);
    } else {
        const size_t base = (size_t)(blockIdx.x - 1024) * 256;
        float d = convert16_dot(W, E, g_wh, base + threadIdx.x);
#pragma unroll
        for (int o = 16; o > 0; o >>= 1)
            d += __shfl_down_sync(0xffffffffu, d, o);
        const int w = threadIdx.x >> 5;
        if ((threadIdx.x & 31) == 0) red[w] = d;
        __syncthreads();
        if (threadIdx.x < 4) {
            int row = (int)(base >> 6) + threadIdx.x;   // 4 rows per block
            g_diag[row] = red[2 * threadIdx.x] + red[2 * threadIdx.x + 1] + b[row];
        }
    }
}

// ---------------------------------------------------------------------------
// Kernel: C[m,n] = sum_k X[m,k]*W[n,k] + diag[n]
// fp16 mma m16n8k16, 4 warps x (64x64), 3-stage cp.async, BK=64,
// XOR-swizzled 128B rows, ks-level fragment double-buffer,
// single barrier per chunk.   (R11/R13 gemm — best measured: 98.6 us)
// ---------------------------------------------------------------------------
__global__ void __launch_bounds__(128, 2)
gemm_fp16_kernel(float* __restrict__ C) {
    extern __shared__ char smem[];

    const int tid = threadIdx.x;
    const int lane = tid & 31;
    const int wid = tid >> 5;       // 0..3
    const int warp_m = wid >> 1;    // 0..1
    const int warp_n = wid & 1;     // 0..1

    const int m0 = blockIdx.y * BM;
    const int n0 = blockIdx.x * BN;

    const __half* Ag = g_xh + (size_t)m0 * HDIM;
    const __half* Bg = g_wh + (size_t)n0 * HDIM;

    auto load_stage = [&](int s, int kt) {
        char* as = smem + s * STAGE_BYTES;
        char* bs = as + TILE_BYTES;
        const int k0 = kt * BK;
#pragma unroll
        for (int j = 0; j < 8; j++) {
            int c = j * 128 + tid;        // 0..1023
            int row = c >> 3;             // 0..127
            int ch = c & 7;               // 16B chunk
            int g = ch >> 1, h = ch & 1;
            uint32_t dst = (uint32_t)(row * 128 + (((g ^ (row & 3)) << 1) | h) * 16);
            cp_async16(as + dst, Ag + (size_t)row * HDIM + k0 + ch * 8);
            cp_async16(bs + dst, Bg + (size_t)row * HDIM + k0 + ch * 8);
        }
        cp_commit();
    };

    float acc[32][4];
#pragma unroll
    for (int i = 0; i < 32; i++)
#pragma unroll
        for (int j = 0; j < 4; j++) acc[i][j] = 0.f;

    // Fragment base offsets (swizzle group field = bits [5:6])
    const int t2 = (lane & 3) * 8;
    uint32_t abase[4], bbase[8];
#pragma unroll
    for (int mt = 0; mt < 4; mt++) {
        int r = warp_m * 64 + mt * 16 + (lane >> 2);
        abase[mt] = (uint32_t)(r * 128 + ((r & 3) << 5) + t2);
    }
#pragma unroll
    for (int nt = 0; nt < 8; nt++) {
        int n = warp_n * 64 + nt * 8 + (lane >> 2);
        bbase[nt] = (uint32_t)(n * 128 + ((n & 3) << 5) + t2);
    }

    // Double-buffered fragments
    uint2 afr[2][4][2];
    uint2 bfr[2][8];

    // Prologue: stages 0..1 in flight
#pragma unroll
    for (int s = 0; s < STAGES - 1; s++) load_stage(s, s);

    for (int kt = 0; kt < KT_CNT; kt++) {
        cp_wait<STAGES - 2>();
        __syncthreads();   // sole barrier: orders prior-stage reads before overwrite

        if (kt + STAGES - 1 < KT_CNT)
            load_stage((kt + STAGES - 1) % STAGES, kt + STAGES - 1);
        else
            cp_commit();   // keep group count consistent

        const char* as = smem + (kt % STAGES) * STAGE_BYTES;
        const char* bs = as + TILE_BYTES;

        // Load ks=0 fragments into buffer 0
#pragma unroll
        for (int mt = 0; mt < 4; mt++) {
            afr[0][mt][0] = *reinterpret_cast<const uint2*>(as + abase[mt]);
            afr[0][mt][1] = *reinterpret_cast<const uint2*>(as + abase[mt] + 8 * 128);
        }
#pragma unroll
        for (int nt = 0; nt < 8; nt++)
            bfr[0][nt] = *reinterpret_cast<const uint2*>(bs + bbase[nt]);

#pragma unroll
        for (int ks = 0; ks < BK / 16; ks++) {   // 4 k16-groups
            const int cur = ks & 1;
            // Prefetch ks+1 fragments before this group's mma block
            if (ks < BK / 16 - 1) {
                const int nxt = (ks + 1) & 1;
                const uint32_t xr = (uint32_t)((ks + 1) << 5);
#pragma unroll
                for (int mt = 0; mt < 4; mt++) {
                    uint32_t off = abase[mt] ^ xr;
                    afr[nxt][mt][0] = *reinterpret_cast<const uint2*>(as + off);
                    afr[nxt][mt][1] = *reinterpret_cast<const uint2*>(as + off + 8 * 128);
                }
#pragma unroll
                for (int nt = 0; nt < 8; nt++)
                    bfr[nxt][nt] = *reinterpret_cast<const uint2*>(bs + (bbase[nt] ^ xr));
            }
#pragma unroll
            for (int mt = 0; mt < 4; mt++)
#pragma unroll
                for (int nt = 0; nt < 8; nt++)
                    mma_fp16(acc[mt * 8 + nt][0], acc[mt * 8 + nt][1],
                             acc[mt * 8 + nt][2], acc[mt * 8 + nt][3],
                             afr[cur][mt][0].x, afr[cur][mt][1].x,
                             afr[cur][mt][0].y, afr[cur][mt][1].y,
                             bfr[cur][nt].x, bfr[cur][nt].y);
        }
        // no end-of-chunk barrier: next iteration's top barrier provides the guard
    }

    // Epilogue: + diag[n], float2 stores
#pragma unroll
    for (int mt = 0; mt < 4; mt++) {
#pragma unroll
        for (int nt = 0; nt < 8; nt++) {
            int r = m0 + warp_m * 64 + mt * 16 + (lane >> 2);
            int c = n0 + warp_n * 64 + nt * 8 + 2 * (lane & 3);
            float2 dg = *reinterpret_cast<const float2*>(&g_diag[c]);
            float2 v0 = make_float2(acc[mt * 8 + nt][0] + dg.x,
                                    acc[mt * 8 + nt][1] + dg.y);
            float2 v1 = make_float2(acc[mt * 8 + nt][2] + dg.x,
                                    acc[mt * 8 + nt][3] + dg.y);
            *reinterpret_cast<float2*>(C + (size_t)r * LDIM + c) = v0;
            *reinterpret_cast<float2*>(C + (size_t)(r + 8) * LDIM + c) = v1;
        }
    }
}

// ---------------------------------------------------------------------------
// Launch
// ---------------------------------------------------------------------------
extern "C" void kernel_launch(void* const* d_in, const int* in_sizes, int n_in,
                              void* d_out, int out_size) {
    const float* x = (const float*)d_in[0];   // bert_output [B,H]
    const float* E = (const float*)d_in[1];   // label_embed [L,H]
    const float* W = (const float*)d_in[2];   // W [L,H]
    const float* b = (const float*)d_in[3];   // b [L]
    float* out = (float*)d_out;               // [B,L]

    prep_kernel<<<2048, 256>>>(x, E, W, b);

    cudaFuncSetAttribute(gemm_fp16_kernel,
                         cudaFuncAttributeMaxDynamicSharedMemorySize, SMEM_BYTES);
    dim3 grid(LDIM / BN, BDIM / BM);
    gemm_fp16_kernel<<<grid, 128, SMEM_BYTES>>>(out);
}